// round 1
// baseline (speedup 1.0000x reference)
#include <cuda_runtime.h>
#include <math.h>

#define T 2048
#define DIM 768
#define NH 12
#define HD 64

// Scratch (allocation-free: __device__ globals)
__device__ float g_qkv[3][T * DIM];   // raw q,k,v projections, [t][768] layout
__device__ float g_q[T * DIM];        // [h][t][64]
__device__ float g_k[T * DIM];        // [h][t][64]
__device__ float g_v[T * DIM];        // [h][t][64]
__device__ float g_att[T * DIM];      // attention output, [t][768] layout

// ---------------------------------------------------------------------------
// SGEMM-NT tile: C[m][n] = sum_k A[m*DIM+k] * B[n*DIM+k]
// 64x64 C tile per block, BK=16, 256 threads, 4x4 microtile per thread.
// ---------------------------------------------------------------------------
__device__ __forceinline__ void sgemm_nt_tile(const float* __restrict__ A,
                                              const float* __restrict__ B,
                                              float* __restrict__ C) {
    __shared__ float As[16][64];
    __shared__ float Bs[16][64];
    const int tid = threadIdx.x;
    const int tx = tid & 15, ty = tid >> 4;
    const int m0 = blockIdx.y * 64, n0 = blockIdx.x * 64;
    const int lrow = tid >> 2;            // 0..63
    const int lc4 = (tid & 3) * 4;        // 0,4,8,12

    float acc[4][4] = {};

    const float* Ap = A + (m0 + lrow) * DIM + lc4;
    const float* Bp = B + (n0 + lrow) * DIM + lc4;

    for (int k0 = 0; k0 < DIM; k0 += 16) {
        float4 a = *(const float4*)(Ap + k0);
        float4 b = *(const float4*)(Bp + k0);
        __syncthreads();
        As[lc4 + 0][lrow] = a.x; As[lc4 + 1][lrow] = a.y;
        As[lc4 + 2][lrow] = a.z; As[lc4 + 3][lrow] = a.w;
        Bs[lc4 + 0][lrow] = b.x; Bs[lc4 + 1][lrow] = b.y;
        Bs[lc4 + 2][lrow] = b.z; Bs[lc4 + 3][lrow] = b.w;
        __syncthreads();
#pragma unroll
        for (int k = 0; k < 16; k++) {
            float4 av = *(const float4*)&As[k][ty * 4];
            float4 bv = *(const float4*)&Bs[k][tx * 4];
            float a4[4] = {av.x, av.y, av.z, av.w};
            float b4[4] = {bv.x, bv.y, bv.z, bv.w};
#pragma unroll
            for (int i = 0; i < 4; i++)
#pragma unroll
                for (int j = 0; j < 4; j++)
                    acc[i][j] += a4[i] * b4[j];
        }
    }
#pragma unroll
    for (int i = 0; i < 4; i++) {
        float4 o = make_float4(acc[i][0], acc[i][1], acc[i][2], acc[i][3]);
        *(float4*)&C[(m0 + ty * 4 + i) * DIM + n0 + tx * 4] = o;
    }
}

// QKV projection: blockIdx.z selects weight/output
__global__ void gemm_qkv_kernel(const float* __restrict__ x,
                                const float* __restrict__ Wq,
                                const float* __restrict__ Wk,
                                const float* __restrict__ Wv) {
    const int z = blockIdx.z;
    const float* B = (z == 0) ? Wq : (z == 1) ? Wk : Wv;
    sgemm_nt_tile(x, B, &g_qkv[z][0]);
}

// Output projection
__global__ void gemm_out_kernel(const float* __restrict__ Wp,
                                float* __restrict__ out) {
    sgemm_nt_tile(g_att, Wp, out);
}

// ---------------------------------------------------------------------------
// Epilogue: v = (1-l)*v + l*vi ; q,k = rope(rmsnorm(q|k)); relayout to [h][t][64]
// One warp per (t, head).
// ---------------------------------------------------------------------------
__global__ void qkv_epilogue_kernel(const float* __restrict__ vi,
                                    const float* __restrict__ lamb) {
    const int w = (blockIdx.x * blockDim.x + threadIdx.x) >> 5;
    const int lane = threadIdx.x & 31;
    if (w >= T * NH) return;
    const int t = w / NH;
    const int h = w % NH;

    const int src = t * DIM + h * HD;          // [t][768] layout offset
    const int dst = (h * T + t) * HD;          // [h][t][64] layout offset

    // RoPE angle: inv_freq = 10000^(-lane/32); pairs are (lane, lane+32)
    const float invf = (float)pow(10000.0, -(double)lane / 32.0);
    const float ang = (float)t * invf;
    float sa, ca;
    sincosf(ang, &sa, &ca);

    const float eps = 1.1920929e-07f;  // fp32 machine epsilon (jnp.finfo.eps)

    // ---- q: rmsnorm + rope ----
    {
        float a = g_qkv[0][src + lane];
        float b = g_qkv[0][src + 32 + lane];
        float ss = a * a + b * b;
#pragma unroll
        for (int m = 16; m >= 1; m >>= 1) ss += __shfl_xor_sync(0xffffffffu, ss, m);
        float r = rsqrtf(ss * (1.0f / 64.0f) + eps);
        a *= r; b *= r;
        g_q[dst + lane]      = a * ca + b * sa;
        g_q[dst + 32 + lane] = -a * sa + b * ca;
    }
    // ---- k: rmsnorm + rope ----
    {
        float a = g_qkv[1][src + lane];
        float b = g_qkv[1][src + 32 + lane];
        float ss = a * a + b * b;
#pragma unroll
        for (int m = 16; m >= 1; m >>= 1) ss += __shfl_xor_sync(0xffffffffu, ss, m);
        float r = rsqrtf(ss * (1.0f / 64.0f) + eps);
        a *= r; b *= r;
        g_k[dst + lane]      = a * ca + b * sa;
        g_k[dst + 32 + lane] = -a * sa + b * ca;
    }
    // ---- v: lambda mix ----
    {
        const float l = lamb[0];
        float va = g_qkv[2][src + lane];
        float vb = g_qkv[2][src + 32 + lane];
        float ia = vi[src + lane];
        float ib = vi[src + 32 + lane];
        g_v[dst + lane]      = (1.0f - l) * va + l * ia;
        g_v[dst + 32 + lane] = (1.0f - l) * vb + l * ib;
    }
}

// ---------------------------------------------------------------------------
// Flash attention, causal. Block per (q-tile of 64, head). 256 threads,
// each thread owns a 4x4 fragment. P reuses the K smem buffer (48KB total).
// ---------------------------------------------------------------------------
__global__ void attn_kernel() {
    __shared__ float Qs[64][64];
    __shared__ float KP[64][64];   // K tile, then overwritten with P
    __shared__ float Vs[64][64];

    const int qt = blockIdx.x;
    const int h = blockIdx.y;
    const int tid = threadIdx.x;
    const int tx = tid & 15, ty = tid >> 4;
    const int q0 = qt * 64;

    const float* qh = g_q + h * T * HD;
    const float* kh = g_k + h * T * HD;
    const float* vh = g_v + h * T * HD;

    // load Q tile
    for (int i = tid; i < 64 * 16; i += 256) {
        int r = i >> 4, c4 = (i & 15) * 4;
        *(float4*)&Qs[r][c4] = *(const float4*)&qh[(q0 + r) * HD + c4];
    }

    float O[4][4] = {};
    float mrow[4] = {-INFINITY, -INFINITY, -INFINITY, -INFINITY};
    float lrow[4] = {};

    for (int kt = 0; kt <= qt; kt++) {
        __syncthreads();  // protect KP (P) / Vs from previous iteration
        for (int i = tid; i < 64 * 16; i += 256) {
            int r = i >> 4, c4 = (i & 15) * 4;
            *(float4*)&KP[r][c4] = *(const float4*)&kh[(kt * 64 + r) * HD + c4];
            *(float4*)&Vs[r][c4] = *(const float4*)&vh[(kt * 64 + r) * HD + c4];
        }
        __syncthreads();

        // S = Q . K^T
        float S[4][4] = {};
#pragma unroll
        for (int dd = 0; dd < 16; dd++) {
            float4 qa[4], kb[4];
#pragma unroll
            for (int i = 0; i < 4; i++) qa[i] = *(const float4*)&Qs[ty * 4 + i][dd * 4];
#pragma unroll
            for (int j = 0; j < 4; j++) kb[j] = *(const float4*)&KP[tx * 4 + j][dd * 4];
#pragma unroll
            for (int i = 0; i < 4; i++)
#pragma unroll
                for (int j = 0; j < 4; j++)
                    S[i][j] += qa[i].x * kb[j].x + qa[i].y * kb[j].y +
                               qa[i].z * kb[j].z + qa[i].w * kb[j].w;
        }

        // scale + causal mask (only the diagonal tile needs masking)
        const bool diag = (kt == qt);
#pragma unroll
        for (int i = 0; i < 4; i++)
#pragma unroll
            for (int j = 0; j < 4; j++) {
                S[i][j] *= 0.125f;  // 1/sqrt(64)
                if (diag && (tx * 4 + j) > (ty * 4 + i)) S[i][j] = -INFINITY;
            }

        // online softmax (row reductions across the 16 tx lanes)
#pragma unroll
        for (int i = 0; i < 4; i++) {
            float mx = fmaxf(fmaxf(S[i][0], S[i][1]), fmaxf(S[i][2], S[i][3]));
#pragma unroll
            for (int m = 8; m >= 1; m >>= 1) mx = fmaxf(mx, __shfl_xor_sync(0xffffffffu, mx, m));
            float mnew = fmaxf(mrow[i], mx);
            float alpha = expf(mrow[i] - mnew);
            mrow[i] = mnew;
            float rs = 0.0f;
#pragma unroll
            for (int j = 0; j < 4; j++) {
                S[i][j] = expf(S[i][j] - mnew);
                rs += S[i][j];
            }
#pragma unroll
            for (int m = 8; m >= 1; m >>= 1) rs += __shfl_xor_sync(0xffffffffu, rs, m);
            lrow[i] = lrow[i] * alpha + rs;
#pragma unroll
            for (int j = 0; j < 4; j++) O[i][j] *= alpha;
        }

        __syncthreads();  // everyone done reading KP as K
#pragma unroll
        for (int i = 0; i < 4; i++)
            *(float4*)&KP[ty * 4 + i][tx * 4] = make_float4(S[i][0], S[i][1], S[i][2], S[i][3]);
        __syncthreads();

        // O += P . V
#pragma unroll
        for (int kk = 0; kk < 16; kk++) {
            float4 pa[4], vb[4];
#pragma unroll
            for (int i = 0; i < 4; i++) pa[i] = *(const float4*)&KP[ty * 4 + i][kk * 4];
#pragma unroll
            for (int j = 0; j < 4; j++) vb[j] = *(const float4*)&Vs[kk * 4 + j][tx * 4];
#pragma unroll
            for (int i = 0; i < 4; i++) {
                O[i][0] += pa[i].x * vb[0].x + pa[i].y * vb[1].x + pa[i].z * vb[2].x + pa[i].w * vb[3].x;
                O[i][1] += pa[i].x * vb[0].y + pa[i].y * vb[1].y + pa[i].z * vb[2].y + pa[i].w * vb[3].y;
                O[i][2] += pa[i].x * vb[0].z + pa[i].y * vb[1].z + pa[i].z * vb[2].z + pa[i].w * vb[3].z;
                O[i][3] += pa[i].x * vb[0].w + pa[i].y * vb[1].w + pa[i].z * vb[2].w + pa[i].w * vb[3].w;
            }
        }
    }

    // normalize and write out in [t][768] layout
#pragma unroll
    for (int i = 0; i < 4; i++) {
        float inv = 1.0f / lrow[i];
        float4 o = make_float4(O[i][0] * inv, O[i][1] * inv, O[i][2] * inv, O[i][3] * inv);
        *(float4*)&g_att[(q0 + ty * 4 + i) * DIM + h * HD + tx * 4] = o;
    }
}

// ---------------------------------------------------------------------------
extern "C" void kernel_launch(void* const* d_in, const int* in_sizes, int n_in,
                              void* d_out, int out_size) {
    const float* x    = (const float*)d_in[0];
    const float* vi   = (const float*)d_in[1];
    const float* Wq   = (const float*)d_in[2];
    const float* Wk   = (const float*)d_in[3];
    const float* Wv   = (const float*)d_in[4];
    const float* Wp   = (const float*)d_in[5];
    const float* lamb = (const float*)d_in[6];
    float* out = (float*)d_out;

    dim3 gqkv(DIM / 64, T / 64, 3);
    gemm_qkv_kernel<<<gqkv, 256>>>(x, Wq, Wk, Wv);

    qkv_epilogue_kernel<<<(T * NH * 32) / 256, 256>>>(vi, lamb);

    dim3 gattn(T / 64, NH, 1);
    attn_kernel<<<gattn, 256>>>();

    dim3 gout(DIM / 64, T / 64, 1);
    gemm_out_kernel<<<gout, 256>>>(Wp, out);
}

// round 2
// speedup vs baseline: 1.3845x; 1.3845x over previous
#include <cuda_runtime.h>
#include <mma.h>
#include <math.h>

using namespace nvcuda;

#define T 2048
#define DIM 768
#define NH 12
#define HD 64

// Scratch (allocation-free: __device__ globals)
__device__ float g_qkv[3][T * DIM];   // raw q,k,v projections, [t][768] layout
__device__ float g_q[T * DIM];        // [h][t][64]
__device__ float g_k[T * DIM];        // [h][t][64]
__device__ float g_v[T * DIM];        // [h][t][64]
__device__ float g_att[T * DIM];      // attention output, [t][768] layout

// ---------------------------------------------------------------------------
// TF32 wmma GEMM-NT: C[m][n] = sum_k A[m*DIM+k] * B[n*DIM+k]
// Block tile 128x64, 8 warps (4x2), warp tile 32x32 (2x2 m16n16k8 frags), BK=16.
// ---------------------------------------------------------------------------
#define BM 128
#define BN 64
#define BK 16

__device__ __forceinline__ void gemm_tile_tf32(const float* __restrict__ A,
                                               const float* __restrict__ B,
                                               float* __restrict__ C) {
    __shared__ float As[BM][BK];   // [m][k]
    __shared__ float Bs[BN][BK];   // [n][k]
    const int tid = threadIdx.x;
    const int wid = tid >> 5;
    const int m0 = blockIdx.y * BM, n0 = blockIdx.x * BN;
    const int warp_m = wid >> 1;   // 0..3
    const int warp_n = wid & 1;    // 0..1

    wmma::fragment<wmma::accumulator, 16, 16, 8, float> acc[2][2];
#pragma unroll
    for (int i = 0; i < 2; i++)
#pragma unroll
        for (int j = 0; j < 2; j++) wmma::fill_fragment(acc[i][j], 0.0f);

    for (int k0 = 0; k0 < DIM; k0 += BK) {
        __syncthreads();
#pragma unroll
        for (int v = tid; v < BM * BK / 4; v += 256) {
            int r = v >> 2, c4 = (v & 3) * 4;
            float4 a = *(const float4*)&A[(m0 + r) * DIM + k0 + c4];
            As[r][c4 + 0] = wmma::__float_to_tf32(a.x);
            As[r][c4 + 1] = wmma::__float_to_tf32(a.y);
            As[r][c4 + 2] = wmma::__float_to_tf32(a.z);
            As[r][c4 + 3] = wmma::__float_to_tf32(a.w);
        }
        {
            int v = tid;  // BN*BK/4 == 256
            int r = v >> 2, c4 = (v & 3) * 4;
            float4 b = *(const float4*)&B[(n0 + r) * DIM + k0 + c4];
            Bs[r][c4 + 0] = wmma::__float_to_tf32(b.x);
            Bs[r][c4 + 1] = wmma::__float_to_tf32(b.y);
            Bs[r][c4 + 2] = wmma::__float_to_tf32(b.z);
            Bs[r][c4 + 3] = wmma::__float_to_tf32(b.w);
        }
        __syncthreads();
#pragma unroll
        for (int kk = 0; kk < BK; kk += 8) {
            wmma::fragment<wmma::matrix_a, 16, 16, 8, wmma::precision::tf32, wmma::row_major> af[2];
            wmma::fragment<wmma::matrix_b, 16, 16, 8, wmma::precision::tf32, wmma::col_major> bf[2];
#pragma unroll
            for (int i = 0; i < 2; i++)
                wmma::load_matrix_sync(af[i], &As[warp_m * 32 + i * 16][kk], BK);
#pragma unroll
            for (int j = 0; j < 2; j++)
                wmma::load_matrix_sync(bf[j], &Bs[warp_n * 32 + j * 16][kk], BK);
#pragma unroll
            for (int i = 0; i < 2; i++)
#pragma unroll
                for (int j = 0; j < 2; j++)
                    wmma::mma_sync(acc[i][j], af[i], bf[j], acc[i][j]);
        }
    }
#pragma unroll
    for (int i = 0; i < 2; i++)
#pragma unroll
        for (int j = 0; j < 2; j++)
            wmma::store_matrix_sync(
                &C[(m0 + warp_m * 32 + i * 16) * DIM + n0 + warp_n * 32 + j * 16],
                acc[i][j], DIM, wmma::mem_row_major);
}

__global__ void gemm_qkv_kernel(const float* __restrict__ x,
                                const float* __restrict__ Wq,
                                const float* __restrict__ Wk,
                                const float* __restrict__ Wv) {
    const int z = blockIdx.z;
    const float* B = (z == 0) ? Wq : (z == 1) ? Wk : Wv;
    gemm_tile_tf32(x, B, &g_qkv[z][0]);
}

__global__ void gemm_out_kernel(const float* __restrict__ Wp,
                                float* __restrict__ out) {
    gemm_tile_tf32(g_att, Wp, out);
}

// ---------------------------------------------------------------------------
// Epilogue: v = (1-l)*v + l*vi ; q,k = rope(rmsnorm(q|k)); relayout to [h][t][64]
// One warp per (t, head).
// ---------------------------------------------------------------------------
__global__ void qkv_epilogue_kernel(const float* __restrict__ vi,
                                    const float* __restrict__ lamb) {
    const int w = (blockIdx.x * blockDim.x + threadIdx.x) >> 5;
    const int lane = threadIdx.x & 31;
    if (w >= T * NH) return;
    const int t = w / NH;
    const int h = w % NH;

    const int src = t * DIM + h * HD;
    const int dst = (h * T + t) * HD;

    const float invf = (float)pow(10000.0, -(double)lane / 32.0);
    const float ang = (float)t * invf;
    float sa, ca;
    sincosf(ang, &sa, &ca);

    const float eps = 1.1920929e-07f;

    {
        float a = g_qkv[0][src + lane];
        float b = g_qkv[0][src + 32 + lane];
        float ss = a * a + b * b;
#pragma unroll
        for (int m = 16; m >= 1; m >>= 1) ss += __shfl_xor_sync(0xffffffffu, ss, m);
        float r = rsqrtf(ss * (1.0f / 64.0f) + eps);
        a *= r; b *= r;
        g_q[dst + lane]      = a * ca + b * sa;
        g_q[dst + 32 + lane] = -a * sa + b * ca;
    }
    {
        float a = g_qkv[1][src + lane];
        float b = g_qkv[1][src + 32 + lane];
        float ss = a * a + b * b;
#pragma unroll
        for (int m = 16; m >= 1; m >>= 1) ss += __shfl_xor_sync(0xffffffffu, ss, m);
        float r = rsqrtf(ss * (1.0f / 64.0f) + eps);
        a *= r; b *= r;
        g_k[dst + lane]      = a * ca + b * sa;
        g_k[dst + 32 + lane] = -a * sa + b * ca;
    }
    {
        const float l = lamb[0];
        float va = g_qkv[2][src + lane];
        float vb = g_qkv[2][src + 32 + lane];
        float ia = vi[src + lane];
        float ib = vi[src + 32 + lane];
        g_v[dst + lane]      = (1.0f - l) * va + l * ia;
        g_v[dst + 32 + lane] = (1.0f - l) * vb + l * ib;
    }
}

// ---------------------------------------------------------------------------
// Flash attention, causal, TF32 tensor cores for S=QK^T and O+=PV.
// Block per (q-tile of 64, head). 256 threads = 8 warps (4x2 warp grid,
// each warp owns a 16x32 output sub-tile). Softmax is fp32 scalar, 4 threads
// per row. S/P/O staged in dynamic shared memory; accumulators round-trip
// through smem via load/store_matrix_sync (documented layouts only).
// ---------------------------------------------------------------------------
__global__ void attn_kernel() {
    extern __shared__ float sm[];
    float* Qs = sm;              // 64x64 (tf32)
    float* Ks = Qs + 4096;       // 64x64 (tf32)
    float* Vs = Ks + 4096;       // 64x64 (tf32)
    float* Ss = Vs + 4096;       // 64x64 scores -> P (tf32)
    float* Os = Ss + 4096;       // 64x64 fp32 output accumulator
    __shared__ float mrow[64], lrow[64];

    const int qt = blockIdx.x;
    const int h = blockIdx.y;
    const int tid = threadIdx.x;
    const int wid = tid >> 5;
    const int warp_m = wid >> 1;  // 0..3
    const int warp_n = wid & 1;   // 0..1
    const int q0 = qt * 64;

    const float* qh = g_q + h * T * HD;
    const float* kh = g_k + h * T * HD;
    const float* vh = g_v + h * T * HD;

    // load Q tile (tf32)
    for (int v = tid; v < 64 * 16; v += 256) {
        int r = v >> 4, c4 = (v & 15) * 4;
        float4 q = *(const float4*)&qh[(q0 + r) * HD + c4];
        Qs[r * 64 + c4 + 0] = wmma::__float_to_tf32(q.x);
        Qs[r * 64 + c4 + 1] = wmma::__float_to_tf32(q.y);
        Qs[r * 64 + c4 + 2] = wmma::__float_to_tf32(q.z);
        Qs[r * 64 + c4 + 3] = wmma::__float_to_tf32(q.w);
    }
    for (int v = tid; v < 4096; v += 256) Os[v] = 0.0f;
    if (tid < 64) { mrow[tid] = -INFINITY; lrow[tid] = 0.0f; }

    const int row = tid >> 2;       // 0..63 (softmax row)
    const int cg = tid & 3;         // col group, 16 cols each

    for (int kt = 0; kt <= qt; kt++) {
        __syncthreads();  // previous iter's readers of Ks/Vs done
        for (int v = tid; v < 64 * 16; v += 256) {
            int r = v >> 4, c4 = (v & 15) * 4;
            float4 k = *(const float4*)&kh[(kt * 64 + r) * HD + c4];
            float4 vv = *(const float4*)&vh[(kt * 64 + r) * HD + c4];
            Ks[r * 64 + c4 + 0] = wmma::__float_to_tf32(k.x);
            Ks[r * 64 + c4 + 1] = wmma::__float_to_tf32(k.y);
            Ks[r * 64 + c4 + 2] = wmma::__float_to_tf32(k.z);
            Ks[r * 64 + c4 + 3] = wmma::__float_to_tf32(k.w);
            Vs[r * 64 + c4 + 0] = wmma::__float_to_tf32(vv.x);
            Vs[r * 64 + c4 + 1] = wmma::__float_to_tf32(vv.y);
            Vs[r * 64 + c4 + 2] = wmma::__float_to_tf32(vv.z);
            Vs[r * 64 + c4 + 3] = wmma::__float_to_tf32(vv.w);
        }
        __syncthreads();

        // S = Q . K^T  (warp computes 16 rows x 32 cols)
        {
            wmma::fragment<wmma::accumulator, 16, 16, 8, float> sacc[2];
#pragma unroll
            for (int j = 0; j < 2; j++) wmma::fill_fragment(sacc[j], 0.0f);
#pragma unroll
            for (int kk = 0; kk < 64; kk += 8) {
                wmma::fragment<wmma::matrix_a, 16, 16, 8, wmma::precision::tf32, wmma::row_major> af;
                wmma::fragment<wmma::matrix_b, 16, 16, 8, wmma::precision::tf32, wmma::col_major> bf[2];
                wmma::load_matrix_sync(af, &Qs[(warp_m * 16) * 64 + kk], 64);
#pragma unroll
                for (int j = 0; j < 2; j++)
                    wmma::load_matrix_sync(bf[j], &Ks[(warp_n * 32 + j * 16) * 64 + kk], 64);
#pragma unroll
                for (int j = 0; j < 2; j++)
                    wmma::mma_sync(sacc[j], af, bf[j], sacc[j]);
            }
#pragma unroll
            for (int j = 0; j < 2; j++)
                wmma::store_matrix_sync(&Ss[(warp_m * 16) * 64 + warp_n * 32 + j * 16],
                                        sacc[j], 64, wmma::mem_row_major);
        }
        __syncthreads();

        // softmax (scalar, 4 threads per row)
        {
            const bool diag = (kt == qt);
            float vals[16];
            float mx = -INFINITY;
#pragma unroll
            for (int c = 0; c < 16; c++) {
                int cc = cg * 16 + c;
                float s = Ss[row * 64 + cc] * 0.125f;
                if (diag && cc > row) s = -INFINITY;
                vals[c] = s;
                mx = fmaxf(mx, s);
            }
            mx = fmaxf(mx, __shfl_xor_sync(0xffffffffu, mx, 1));
            mx = fmaxf(mx, __shfl_xor_sync(0xffffffffu, mx, 2));
            float mprev = mrow[row];
            float mnew = fmaxf(mprev, mx);
            float alpha = __expf(mprev - mnew);
            float rs = 0.0f;
#pragma unroll
            for (int c = 0; c < 16; c++) {
                float p = __expf(vals[c] - mnew);
                rs += p;
                Ss[row * 64 + cg * 16 + c] = wmma::__float_to_tf32(p);
            }
            rs += __shfl_xor_sync(0xffffffffu, rs, 1);
            rs += __shfl_xor_sync(0xffffffffu, rs, 2);
            if (cg == 0) {
                lrow[row] = lrow[row] * alpha + rs;
                mrow[row] = mnew;
            }
#pragma unroll
            for (int c = 0; c < 16; c++) Os[row * 64 + cg * 16 + c] *= alpha;
        }
        __syncthreads();

        // O += P . V  (warp computes 16 rows x 32 cols of O)
        {
            wmma::fragment<wmma::accumulator, 16, 16, 8, float> oacc[2];
#pragma unroll
            for (int j = 0; j < 2; j++)
                wmma::load_matrix_sync(oacc[j],
                                       &Os[(warp_m * 16) * 64 + warp_n * 32 + j * 16],
                                       64, wmma::mem_row_major);
#pragma unroll
            for (int kk = 0; kk < 64; kk += 8) {
                wmma::fragment<wmma::matrix_a, 16, 16, 8, wmma::precision::tf32, wmma::row_major> af;
                wmma::fragment<wmma::matrix_b, 16, 16, 8, wmma::precision::tf32, wmma::row_major> bf[2];
                wmma::load_matrix_sync(af, &Ss[(warp_m * 16) * 64 + kk], 64);
#pragma unroll
                for (int j = 0; j < 2; j++)
                    wmma::load_matrix_sync(bf[j], &Vs[kk * 64 + warp_n * 32 + j * 16], 64);
#pragma unroll
                for (int j = 0; j < 2; j++)
                    wmma::mma_sync(oacc[j], af, bf[j], oacc[j]);
            }
#pragma unroll
            for (int j = 0; j < 2; j++)
                wmma::store_matrix_sync(&Os[(warp_m * 16) * 64 + warp_n * 32 + j * 16],
                                        oacc[j], 64, wmma::mem_row_major);
        }
    }
    __syncthreads();

    // normalize + write out in [t][768] layout
    {
        float inv = 1.0f / lrow[row];
#pragma unroll
        for (int c = 0; c < 16; c++)
            g_att[(q0 + row) * DIM + h * HD + cg * 16 + c] = Os[row * 64 + cg * 16 + c] * inv;
    }
}

// ---------------------------------------------------------------------------
extern "C" void kernel_launch(void* const* d_in, const int* in_sizes, int n_in,
                              void* d_out, int out_size) {
    const float* x    = (const float*)d_in[0];
    const float* vi   = (const float*)d_in[1];
    const float* Wq   = (const float*)d_in[2];
    const float* Wk   = (const float*)d_in[3];
    const float* Wv   = (const float*)d_in[4];
    const float* Wp   = (const float*)d_in[5];
    const float* lamb = (const float*)d_in[6];
    float* out = (float*)d_out;

    static bool attr_set = false;
    if (!attr_set) {
        cudaFuncSetAttribute(attn_kernel,
                             cudaFuncAttributeMaxDynamicSharedMemorySize,
                             5 * 4096 * sizeof(float));
        attr_set = true;
    }

    dim3 gqkv(DIM / BN, T / BM, 3);
    gemm_qkv_kernel<<<gqkv, 256>>>(x, Wq, Wk, Wv);

    qkv_epilogue_kernel<<<(T * NH * 32) / 256, 256>>>(vi, lamb);

    dim3 gattn(T / 64, NH, 1);
    attn_kernel<<<gattn, 256, 5 * 4096 * sizeof(float)>>>();

    dim3 gout(DIM / BN, T / BM, 1);
    gemm_out_kernel<<<gout, 256>>>(Wp, out);
}